// round 8
// baseline (speedup 1.0000x reference)
#include <cuda_runtime.h>
#include <math.h>

// ---------------------------------------------------------------------------
// b=2, c=512, h=w=64 -> n=4096 points, d=64 features, 5x5 local cov.
// out[b] = concat(mu (64 ch), local cov (25 ch)) -> (2, 89, 64, 64) fp32.
//
// Per batch:
//   K_yy+sigma I = L L^T        (blocked Cholesky NB=128, 32 steps)
//   Linv = L^{-1} explicitly    (recursive doubling, z-batched GEMMs)
//   X  = [K_xy ; ff^T] * Linv^T (ONE triangular-clipped GEMM)
//   mu = X(0:4096) @ X(4096:4160)^T
//   cov[p,q] = K_xx[p,q] - X[p,:].X[q,:]   (5x5 neighbors only)
// ---------------------------------------------------------------------------

#define NPT   4096
#define MROWS 4224
#define NBLK  32

__device__ float g_L [(size_t)NPT * NPT];     // K_yy -> L (lower)
__device__ float g_LI[(size_t)NPT * NPT];     // L^{-1} (lower; upper stays 0)
__device__ float g_X [(size_t)MROWS * NPT];   // [K_xy ; ff^T ; 0]
__device__ float g_X2[(size_t)MROWS * NPT];   // X = g_X * Linv^T
__device__ float g_T [(size_t)4 * 1024 * 1024]; // tree temp (max 2048^2)
__device__ float g_XF[(size_t)NPT * 512];     // x point-major
__device__ float g_MU[(size_t)NPT * 128];
__device__ float g_xn[NPT];
__device__ float g_yn[NPT];

// ---------------- small prep kernels ----------------
__global__ void norms_k(const float* __restrict__ v, float* __restrict__ o) {
    int p = blockIdx.x * blockDim.x + threadIdx.x;
    float s = 0.f;
    for (int ch = 0; ch < 512; ch++) { float t = v[(size_t)ch * NPT + p]; s += t * t; }
    o[p] = sqrtf(s);
}

__global__ void transpose_k(const float* __restrict__ v, float* __restrict__ o) {
    __shared__ float t[32][33];
    int pb = blockIdx.x * 32, cb = blockIdx.y * 32;
    for (int yy = threadIdx.y; yy < 32; yy += 8)
        t[yy][threadIdx.x] = v[(size_t)(cb + yy) * NPT + pb + threadIdx.x];
    __syncthreads();
    for (int yy = threadIdx.y; yy < 32; yy += 8)
        o[(size_t)(pb + yy) * 512 + cb + threadIdx.x] = t[threadIdx.x][yy];
}

__global__ void features_k(const float* __restrict__ pw, const float* __restrict__ pb,
                           float* __restrict__ F) {
    int idx = blockIdx.x * blockDim.x + threadIdx.x;   // 4096*64
    int q = idx & 4095, dch = idx >> 12;
    float gx = (2.f * (float)(q & 63) + 1.f) * (1.f / 64.f) - 1.f;
    float gy = (2.f * (float)(q >> 6) + 1.f) * (1.f / 64.f) - 1.f;
    float ph = pw[dch * 2 + 0] * gx + pw[dch * 2 + 1] * gy + pb[dch];
    F[(size_t)dch * NPT + q] = cosf(25.132741228718345f * ph);   // 8*pi
}

__global__ void zero_rows(float* __restrict__ dst) {
    int i = blockIdx.x * blockDim.x + threadIdx.x;     // 64*4096
    dst[i] = 0.f;
}

__global__ void copy_mu(const float* __restrict__ MU, float* __restrict__ out) {
    int idx = blockIdx.x * blockDim.x + threadIdx.x;   // 64*4096
    int dch = idx >> 12, p = idx & 4095;
    out[(size_t)dch * NPT + p] = MU[(size_t)p * 128 + dch];
}

// ---------------- Gram: C[p,q] = exp(dot/(na nb + eps) - 1) (+sigma diag) ----
__global__ void __launch_bounds__(256) gram_tn(const float* __restrict__ A,
        const float* __restrict__ B, float* __restrict__ Cm,
        const float* __restrict__ na, const float* __restrict__ nb,
        int lowerOnly, float sigmaDiag) {
    int bx = blockIdx.x, by = blockIdx.y;
    if (lowerOnly && bx > by) return;
    __shared__ float As[8][128], Bs[8][128];
    int tid = threadIdx.x;
    int tx = tid & 15, ty = tid >> 4;
    const float* Ab = A + by * 128;
    const float* Bb = B + bx * 128;
    float acc[8][8];
    #pragma unroll
    for (int i = 0; i < 8; i++)
        #pragma unroll
        for (int j = 0; j < 8; j++) acc[i][j] = 0.f;
    int lr = tid >> 5;
    int lc = (tid & 31) << 2;
    for (int k0 = 0; k0 < 512; k0 += 8) {
        float4 av = *(const float4*)(Ab + (size_t)(k0 + lr) * NPT + lc);
        float4 bv = *(const float4*)(Bb + (size_t)(k0 + lr) * NPT + lc);
        *(float4*)&As[lr][lc] = av;
        *(float4*)&Bs[lr][lc] = bv;
        __syncthreads();
        #pragma unroll
        for (int k = 0; k < 8; k++) {
            float a[8], b[8];
            *(float4*)(a)     = *(const float4*)&As[k][ty * 8];
            *(float4*)(a + 4) = *(const float4*)&As[k][ty * 8 + 4];
            *(float4*)(b)     = *(const float4*)&Bs[k][tx * 8];
            *(float4*)(b + 4) = *(const float4*)&Bs[k][tx * 8 + 4];
            #pragma unroll
            for (int i = 0; i < 8; i++)
                #pragma unroll
                for (int j = 0; j < 8; j++) acc[i][j] += a[i] * b[j];
        }
        __syncthreads();
    }
    #pragma unroll
    for (int i = 0; i < 8; i++) {
        int gi = by * 128 + ty * 8 + i;
        float nai = na[gi];
        #pragma unroll
        for (int j = 0; j < 8; j++) {
            int gj = bx * 128 + tx * 8 + j;
            float v = expf(acc[i][j] / (nai * nb[gj] + 1e-6f) - 1.f);
            if (gi == gj) v += sigmaDiag;
            Cm[(size_t)gi * NPT + gj] = v;
        }
    }
}

// ---------------- unified GEMM ------------------------------------------
// transB=0: C = beta*C + alpha * A * B^T ; transB=1: ... A * B
// ktri: 0 none; 1 kHi=(bx+1)*128 (NT, B lower-tri); 2 kLo=bx*128 (NN, B lower);
//       3 kHi=(by+1)*128 (NN, A lower-tri)
// z-batched via element strides sAz/sBz/sCz. triSkip skips bx>by blocks.
__global__ void __launch_bounds__(256) gemmx(const float* __restrict__ A,
        const float* __restrict__ B, float* __restrict__ Cm,
        int K, int lda, int ldb, int ldc,
        long long sAz, long long sBz, long long sCz,
        int transB, float alpha, int beta, int ktri, int triSkip) {
    int bx = blockIdx.x, by = blockIdx.y, bz = blockIdx.z;
    if (triSkip && bx > by) return;
    A += (size_t)bz * sAz; B += (size_t)bz * sBz; Cm += (size_t)bz * sCz;
    int kLo = 0, kHi = K;
    if (ktri == 1) { int h = (bx + 1) * 128; kHi = h < K ? h : K; }
    else if (ktri == 2) kLo = bx * 128;
    else if (ktri == 3) { int h = (by + 1) * 128; kHi = h < K ? h : K; }

    __shared__ float As[8][128], Bs[8][128];
    int tid = threadIdx.x;
    int tx = tid & 15, ty = tid >> 4;
    const float* Ab = A + (size_t)(by * 128) * lda;
    float* Cb = Cm + (size_t)(by * 128) * ldc + bx * 128;
    float acc[8][8];
    #pragma unroll
    for (int i = 0; i < 8; i++)
        #pragma unroll
        for (int j = 0; j < 8; j++) acc[i][j] = 0.f;

    int lrA = tid >> 1, lcA = (tid & 1) << 2;     // A / NT-B staging
    int lrB = tid >> 5, lcB = (tid & 31) << 2;    // NN-B staging
    const float* BbNT = B + (size_t)(bx * 128) * ldb;
    const float* BbNN = B + bx * 128;

    for (int k0 = kLo; k0 < kHi; k0 += 8) {
        float4 av = *(const float4*)(Ab + (size_t)lrA * lda + k0 + lcA);
        As[lcA + 0][lrA] = av.x; As[lcA + 1][lrA] = av.y;
        As[lcA + 2][lrA] = av.z; As[lcA + 3][lrA] = av.w;
        if (transB == 0) {
            float4 bv = *(const float4*)(BbNT + (size_t)lrA * ldb + k0 + lcA);
            Bs[lcA + 0][lrA] = bv.x; Bs[lcA + 1][lrA] = bv.y;
            Bs[lcA + 2][lrA] = bv.z; Bs[lcA + 3][lrA] = bv.w;
        } else {
            float4 bv = *(const float4*)(BbNN + (size_t)(k0 + lrB) * ldb + lcB);
            *(float4*)&Bs[lrB][lcB] = bv;
        }
        __syncthreads();
        #pragma unroll
        for (int k = 0; k < 8; k++) {
            float a[8], b[8];
            *(float4*)(a)     = *(const float4*)&As[k][ty * 8];
            *(float4*)(a + 4) = *(const float4*)&As[k][ty * 8 + 4];
            *(float4*)(b)     = *(const float4*)&Bs[k][tx * 8];
            *(float4*)(b + 4) = *(const float4*)&Bs[k][tx * 8 + 4];
            #pragma unroll
            for (int i = 0; i < 8; i++)
                #pragma unroll
                for (int j = 0; j < 8; j++) acc[i][j] += a[i] * b[j];
        }
        __syncthreads();
    }
    #pragma unroll
    for (int i = 0; i < 8; i++) {
        float4* cp = (float4*)(Cb + (size_t)(ty * 8 + i) * ldc + tx * 8);
        float4 v0, v1;
        v0.x = alpha * acc[i][0]; v0.y = alpha * acc[i][1];
        v0.z = alpha * acc[i][2]; v0.w = alpha * acc[i][3];
        v1.x = alpha * acc[i][4]; v1.y = alpha * acc[i][5];
        v1.z = alpha * acc[i][6]; v1.w = alpha * acc[i][7];
        if (beta) {
            float4 o0 = cp[0], o1 = cp[1];
            v0.x += o0.x; v0.y += o0.y; v0.z += o0.z; v0.w += o0.w;
            v1.x += o1.x; v1.y += o1.y; v1.z += o1.z; v1.w += o1.w;
        }
        cp[0] = v0; cp[1] = v1;
    }
}

// ---------------- 128x128 diag Cholesky + blocked triangular inverse --------
// One block, 128 threads. L stays in Ablk (lda NPT); L^{-1} -> IvBlk (lda NPT).
__global__ void __launch_bounds__(128) potf2_inv(float* __restrict__ Ablk,
                                                 float* __restrict__ IvBlk) {
    extern __shared__ float sm[];
    float* As = sm;                   // 128 x 129
    float* Iv = sm + 128 * 129;       // 128 x 128
    float* W  = sm + 128 * 129 + 128 * 128;   // 16 x 112
    int tid = threadIdx.x;
    for (int idx = tid; idx < 128 * 128; idx += 128) {
        int r = idx >> 7, c = idx & 127;
        As[r * 129 + c] = Ablk[(size_t)r * NPT + c];
        Iv[idx] = 0.f;
    }
    __syncthreads();
    // right-looking Cholesky
    for (int j = 0; j < 128; j++) {
        if (tid == 0) As[j * 129 + j] = sqrtf(As[j * 129 + j]);
        __syncthreads();
        float d = As[j * 129 + j];
        if (tid > j) As[tid * 129 + j] /= d;
        __syncthreads();
        int m = j + 1 + tid;
        if (m < 128) {
            float lm = As[m * 129 + j];
            #pragma unroll 4
            for (int t = j + 1; t < 128; t++)
                As[t * 129 + m] -= As[t * 129 + j] * lm;
        }
        __syncthreads();
    }
    // 16x16 diagonal block inverses (thread = (block db, local col c))
    {
        int db = tid >> 4, c = tid & 15, base = db * 16;
        for (int t = 0; t < 16; t++) {
            float v;
            if (t < c) v = 0.f;
            else if (t == c) v = 1.f / As[(base + t) * 129 + base + c];
            else {
                float s = 0.f;
                for (int m2 = c; m2 < t; m2++)
                    s += As[(base + t) * 129 + base + m2] * Iv[(base + m2) * 128 + base + c];
                v = -s / As[(base + t) * 129 + base + t];
            }
            Iv[(base + t) * 128 + base + c] = v;
        }
    }
    __syncthreads();
    // blocked forward substitution: rows block tb, cols < tb*16
    for (int tb = 1; tb < 8; tb++) {
        int R = tb * 16, ncol = tb * 16, total = 16 * ncol;
        for (int idx = tid; idx < total; idx += 128) {
            int s = idx / ncol, c2 = idx % ncol;
            float a = 0.f;
            for (int m2 = c2; m2 < R; m2++)
                a += As[(R + s) * 129 + m2] * Iv[m2 * 128 + c2];
            W[s * 112 + c2] = a;
        }
        __syncthreads();
        for (int idx = tid; idx < total; idx += 128) {
            int r = idx / ncol, c2 = idx % ncol;
            float a = 0.f;
            for (int s = 0; s <= r; s++)
                a += Iv[(R + r) * 128 + R + s] * W[s * 112 + c2];
            Iv[(R + r) * 128 + c2] = -a;
        }
        __syncthreads();
    }
    for (int idx = tid; idx < 128 * 128; idx += 128) {
        int r = idx >> 7, c = idx & 127;
        Ablk[(size_t)r * NPT + c] = As[r * 129 + c];
        IvBlk[(size_t)r * NPT + c] = Iv[idx];
    }
}

// ---------------- local covariance + Kxx on 5x5 neighborhoods ----------------
__global__ void __launch_bounds__(256) local_k(const float* __restrict__ X,
        const float* __restrict__ XF, const float* __restrict__ xn,
        float* __restrict__ outb) {
    __shared__ __align__(16) float sXp[4096];
    __shared__ __align__(16) float sXf[512];
    __shared__ float sRed[16];
    int p = blockIdx.x, tid = threadIdx.x;
    const float4* Xp4 = (const float4*)(X + (size_t)p * NPT);
    for (int t = tid; t < 1024; t += 256) ((float4*)sXp)[t] = Xp4[t];
    const float4* xf4 = (const float4*)(XF + (size_t)p * 512);
    if (tid < 128) ((float4*)sXf)[tid] = xf4[tid];
    __syncthreads();
    int i0 = p >> 6, j0 = p & 63;
    float nxp = xn[p];
    int warp = tid >> 5, lane = tid & 31;
    for (int kk = 0; kk < 25; kk++) {
        int dr = kk / 5 - 2, dc = kk % 5 - 2;
        int qi = i0 + dr, qj = j0 + dc;
        bool valid = (qi >= 0) & (qi < 64) & (qj >= 0) & (qj < 64);
        __syncthreads();
        if (!valid) {
            if (tid == 0) outb[(size_t)(64 + kk) * NPT + p] = 0.f;
            continue;
        }
        int q = qi * 64 + qj;
        const float4* Xq4 = (const float4*)(X + (size_t)q * NPT);
        float s = 0.f;
        for (int t = tid; t < 1024; t += 256) {
            float4 a = ((const float4*)sXp)[t];
            float4 bq = Xq4[t];
            s += a.x * bq.x + a.y * bq.y + a.z * bq.z + a.w * bq.w;
        }
        float s2 = 0.f;
        const float4* xq4 = (const float4*)(XF + (size_t)q * 512);
        if (tid < 128) {
            float4 a = ((const float4*)sXf)[tid];
            float4 bq = xq4[tid];
            s2 = a.x * bq.x + a.y * bq.y + a.z * bq.z + a.w * bq.w;
        }
        #pragma unroll
        for (int o = 16; o; o >>= 1) {
            s  += __shfl_down_sync(0xffffffffu, s,  o);
            s2 += __shfl_down_sync(0xffffffffu, s2, o);
        }
        if (lane == 0) { sRed[warp] = s; sRed[8 + warp] = s2; }
        __syncthreads();
        if (tid == 0) {
            float ts = 0.f, ts2 = 0.f;
            #pragma unroll
            for (int w = 0; w < 8; w++) { ts += sRed[w]; ts2 += sRed[8 + w]; }
            float kxx = expf(ts2 / (nxp * xn[q] + 1e-6f) - 1.f);
            outb[(size_t)(64 + kk) * NPT + p] = kxx - ts;
        }
    }
}

// ---------------------------------------------------------------------------
extern "C" void kernel_launch(void* const* d_in, const int* in_sizes, int n_in,
                              void* d_out, int out_size) {
    const float* x  = (const float*)d_in[0];
    const float* y  = (const float*)d_in[1];
    const float* pw = (const float*)d_in[2];
    const float* pb = (const float*)d_in[3];
    float* out = (float*)d_out;
    (void)in_sizes; (void)n_in; (void)out_size;

    float *pL, *pLI, *pX, *pX2, *pT, *pXF, *pMU, *pxn, *pyn;
    cudaGetSymbolAddress((void**)&pL,  g_L);
    cudaGetSymbolAddress((void**)&pLI, g_LI);
    cudaGetSymbolAddress((void**)&pX,  g_X);
    cudaGetSymbolAddress((void**)&pX2, g_X2);
    cudaGetSymbolAddress((void**)&pT,  g_T);
    cudaGetSymbolAddress((void**)&pXF, g_XF);
    cudaGetSymbolAddress((void**)&pMU, g_MU);
    cudaGetSymbolAddress((void**)&pxn, g_xn);
    cudaGetSymbolAddress((void**)&pyn, g_yn);

    const int PSMEM = (128 * 129 + 128 * 128 + 16 * 112) * 4;
    cudaFuncSetAttribute(potf2_inv, cudaFuncAttributeMaxDynamicSharedMemorySize, PSMEM);

    for (int b = 0; b < 2; b++) {
        const float* xb = x + (size_t)b * 512 * NPT;
        const float* yb = y + (size_t)b * 512 * NPT;
        float* outb = out + (size_t)b * 89 * NPT;

        norms_k<<<16, 256>>>(xb, pxn);
        norms_k<<<16, 256>>>(yb, pyn);
        transpose_k<<<dim3(128, 16), dim3(32, 8)>>>(xb, pXF);

        gram_tn<<<dim3(32, 32), 256>>>(yb, yb, pL, pyn, pyn, 1, 0.1f);
        gram_tn<<<dim3(32, 32), 256>>>(xb, yb, pX, pxn, pyn, 0, 0.f);
        features_k<<<1024, 256>>>(pw, pb, pX + (size_t)NPT * NPT);
        zero_rows<<<1024, 256>>>(pX + (size_t)(NPT + 64) * NPT);

        // ---- blocked Cholesky; diag inverses land in g_LI diagonal ----
        for (int k = 0; k < NBLK; k++) {
            float* diag = pL  + (size_t)k * 128 * NPT + k * 128;
            float* idia = pLI + (size_t)k * 128 * NPT + k * 128;
            potf2_inv<<<1, 128, PSMEM>>>(diag, idia);
            if (k < NBLK - 1) {
                int rem = NBLK - 1 - k;
                float* panel = pL + (size_t)(k + 1) * 128 * NPT + k * 128;
                // L21 = A21 * iL11^T  (NT, in place)
                gemmx<<<dim3(1, rem), 256>>>(panel, idia, panel,
                        128, NPT, NPT, NPT, 0, 0, 0, /*NT*/0, 1.f, 0, 0, 0);
                // A22 -= L21 L21^T (lower)
                float* trail = pL + (size_t)(k + 1) * 128 * NPT + (k + 1) * 128;
                gemmx<<<dim3(rem, rem), 256>>>(panel, panel, trail,
                        128, NPT, NPT, NPT, 0, 0, 0, /*NT*/0, -1.f, 1, 0, 1);
            }
        }

        // ---- Linv by recursive doubling: iL21 = -iL22 (L21 iL11) ----
        for (int m = 128; m < NPT; m <<= 1) {
            int nodes = NPT / (2 * m);
            int nb = m / 128;
            long long sNode = (long long)(2 * m) * (NPT + 1);
            // T = L21 * iL11   (NN, kLo = bx*128)
            gemmx<<<dim3(nb, nb, nodes), 256>>>(
                    pL + (size_t)m * NPT, pLI, pT,
                    m, NPT, NPT, m,
                    sNode, sNode, (long long)m * m,
                    /*NN*/1, 1.f, 0, 2, 0);
            // iL21 = -iL22 * T (NN, kHi = (by+1)*128)
            gemmx<<<dim3(nb, nb, nodes), 256>>>(
                    pLI + (size_t)m * NPT + m, pT, pLI + (size_t)m * NPT,
                    m, NPT, m, NPT,
                    sNode, (long long)m * m, sNode,
                    /*NN*/1, -1.f, 0, 3, 0);
        }

        // ---- X = [Kxy ; ff^T] * Linv^T  (NT, kHi = (bx+1)*128) ----
        gemmx<<<dim3(32, MROWS / 128), 256>>>(pX, pLI, pX2,
                NPT, NPT, NPT, NPT, 0, 0, 0, /*NT*/0, 1.f, 0, 1, 0);

        // ---- mu = X(0:4096) @ u^T (u^T = rows 4096..4223; pads are zero) ----
        gemmx<<<dim3(1, 32), 256>>>(pX2, pX2 + (size_t)NPT * NPT, pMU,
                NPT, NPT, NPT, 128, 0, 0, 0, /*NT*/0, 1.f, 0, 0, 0);
        copy_mu<<<1024, 256>>>(pMU, outb);

        // ---- local covariance channels ----
        local_k<<<4096, 256>>>(pX2, pXF, pxn, outb);
    }
}

// round 9
// speedup vs baseline: 1.7868x; 1.7868x over previous
#include <cuda_runtime.h>
#include <math.h>

// ---------------------------------------------------------------------------
// b=2, c=512, h=w=64 -> n=4096 points, d=64 features, 5x5 local cov.
// out[b] = concat(mu (64 ch), local cov (25 ch)) -> (2, 89, 64, 64) fp32.
//
// Per batch (all launches z-batched over both batches):
//   K_yy+sigma I = L L^T  (blocked Cholesky NB=128)
//   X = [K_xy ; ff^T] L^{-T}  (right-TRSM column sweep, in place)
//   mu = X(0:4096) @ X(4096:4160)^T       (split-K)
//   cov[p,q] = K_xx[p,q] - X[p,:].X[q,:]  (5x5 neighbors only)
// ---------------------------------------------------------------------------

#define NPT   4096
#define MROWS 4224
#define NBLK  32
#define LNN   ((size_t)NPT * NPT)
#define XNN   ((size_t)MROWS * NPT)
#define LINB  (32 * 128 * 128)

__device__ float g_L  [2 * LNN];            // K_yy -> L (lower), per batch
__device__ float g_X  [2 * XNN];            // [K_xy ; ff^T ; 0] -> X (in place)
__device__ float g_Li [2 * LINB];           // compact 128x128 diag inverses
__device__ float g_XF [2 * (size_t)NPT * 512];
__device__ float g_MUP[2 * 8 * (size_t)NPT * 128];  // split-K mu partials
__device__ float g_xn [2 * NPT];
__device__ float g_yn [2 * NPT];

// ---------------- prep kernels (z = batch) ----------------
__global__ void norms2_k(const float* __restrict__ x, const float* __restrict__ y,
                         float* __restrict__ xn, float* __restrict__ yn) {
    int b = blockIdx.z, sel = blockIdx.y;
    const float* v = (sel ? y : x) + (size_t)b * 512 * NPT;
    float* o = (sel ? yn : xn) + (size_t)b * NPT;
    int p = blockIdx.x * blockDim.x + threadIdx.x;
    float s = 0.f;
    for (int ch = 0; ch < 512; ch++) { float t = v[(size_t)ch * NPT + p]; s += t * t; }
    o[p] = sqrtf(s);
}

__global__ void transpose_k(const float* __restrict__ x, float* __restrict__ of) {
    int b = blockIdx.z;
    const float* v = x + (size_t)b * 512 * NPT;
    float* o = of + (size_t)b * NPT * 512;
    __shared__ float t[32][33];
    int pb = blockIdx.x * 32, cb = blockIdx.y * 32;
    for (int yy = threadIdx.y; yy < 32; yy += 8)
        t[yy][threadIdx.x] = v[(size_t)(cb + yy) * NPT + pb + threadIdx.x];
    __syncthreads();
    for (int yy = threadIdx.y; yy < 32; yy += 8)
        o[(size_t)(pb + yy) * 512 + cb + threadIdx.x] = t[threadIdx.x][yy];
}

__global__ void features_k(const float* __restrict__ pw, const float* __restrict__ pb,
                           float* __restrict__ X) {
    int b = blockIdx.z;
    int idx = blockIdx.x * blockDim.x + threadIdx.x;   // 4096*64
    int q = idx & 4095, dch = idx >> 12;
    float gx = (2.f * (float)(q & 63) + 1.f) * (1.f / 64.f) - 1.f;
    float gy = (2.f * (float)(q >> 6) + 1.f) * (1.f / 64.f) - 1.f;
    float ph = pw[dch * 2 + 0] * gx + pw[dch * 2 + 1] * gy + pb[dch];
    X[(size_t)b * XNN + LNN + (size_t)dch * NPT + q] = cosf(25.132741228718345f * ph);
}

__global__ void zero_rows(float* __restrict__ X) {
    int b = blockIdx.z;
    int i = blockIdx.x * blockDim.x + threadIdx.x;     // 64*4096
    X[(size_t)b * XNN + (size_t)(NPT + 64) * NPT + i] = 0.f;
}

// ---------------- Gram: C[p,q] = exp(dot/(na nb + eps) - 1) (+sigma diag) ----
__global__ void __launch_bounds__(256) gram_tn(const float* __restrict__ A,
        const float* __restrict__ B, float* __restrict__ Cm,
        const float* __restrict__ na, const float* __restrict__ nb,
        int lowerOnly, float sigmaDiag, long long sCz) {
    int bx = blockIdx.x, by = blockIdx.y, bz = blockIdx.z;
    if (lowerOnly && bx > by) return;
    A  += (size_t)bz * 512 * NPT;
    B  += (size_t)bz * 512 * NPT;
    Cm += (size_t)bz * sCz;
    na += (size_t)bz * NPT;
    nb += (size_t)bz * NPT;
    __shared__ float As[8][128], Bs[8][128];
    int tid = threadIdx.x;
    int tx = tid & 15, ty = tid >> 4;
    const float* Ab = A + by * 128;
    const float* Bb = B + bx * 128;
    float acc[8][8];
    #pragma unroll
    for (int i = 0; i < 8; i++)
        #pragma unroll
        for (int j = 0; j < 8; j++) acc[i][j] = 0.f;
    int lr = tid >> 5;
    int lc = (tid & 31) << 2;
    for (int k0 = 0; k0 < 512; k0 += 8) {
        float4 av = *(const float4*)(Ab + (size_t)(k0 + lr) * NPT + lc);
        float4 bv = *(const float4*)(Bb + (size_t)(k0 + lr) * NPT + lc);
        *(float4*)&As[lr][lc] = av;
        *(float4*)&Bs[lr][lc] = bv;
        __syncthreads();
        #pragma unroll
        for (int k = 0; k < 8; k++) {
            float a[8], b[8];
            *(float4*)(a)     = *(const float4*)&As[k][ty * 8];
            *(float4*)(a + 4) = *(const float4*)&As[k][ty * 8 + 4];
            *(float4*)(b)     = *(const float4*)&Bs[k][tx * 8];
            *(float4*)(b + 4) = *(const float4*)&Bs[k][tx * 8 + 4];
            #pragma unroll
            for (int i = 0; i < 8; i++)
                #pragma unroll
                for (int j = 0; j < 8; j++) acc[i][j] += a[i] * b[j];
        }
        __syncthreads();
    }
    #pragma unroll
    for (int i = 0; i < 8; i++) {
        int gi = by * 128 + ty * 8 + i;
        float nai = na[gi];
        #pragma unroll
        for (int j = 0; j < 8; j++) {
            int gj = bx * 128 + tx * 8 + j;
            float v = expf(acc[i][j] / (nai * nb[gj] + 1e-6f) - 1.f);
            if (gi == gj) v += sigmaDiag;
            Cm[(size_t)gi * NPT + gj] = v;
        }
    }
}

// ---------------- GEMM-NT, z-batched --------------------------------------
// mode 0: C -= A*B^T ; mode 1: C = A*B^T. triSkip skips bx>by.
// kSplit>0: bx selects k-chunk [bx*kSplit, +kSplit); C has one 128-wide column
// block at chunk offset bx*NPT*128 (mu split-K partials).
__global__ void __launch_bounds__(256) gemm_nt(const float* __restrict__ A,
        const float* __restrict__ B, float* __restrict__ Cm,
        int K, int lda, int ldb, int ldc,
        long long sAz, long long sBz, long long sCz,
        int mode, int triSkip, int kSplit) {
    int bx = blockIdx.x, by = blockIdx.y, bz = blockIdx.z;
    if (triSkip && bx > by) return;
    A += (size_t)bz * sAz; B += (size_t)bz * sBz; Cm += (size_t)bz * sCz;
    int kLo = 0, kHi = K;
    float* Cb;
    const float* Bb;
    if (kSplit) {
        kLo = bx * kSplit; kHi = kLo + kSplit;
        Cb = Cm + (size_t)bx * NPT * 128 + (size_t)(by * 128) * ldc;
        Bb = B;
    } else {
        Cb = Cm + (size_t)(by * 128) * ldc + bx * 128;
        Bb = B + (size_t)(bx * 128) * ldb;
    }
    __shared__ float As[8][128], Bs[8][128];
    int tid = threadIdx.x;
    int tx = tid & 15, ty = tid >> 4;
    const float* Ab = A + (size_t)(by * 128) * lda;
    float acc[8][8];
    #pragma unroll
    for (int i = 0; i < 8; i++)
        #pragma unroll
        for (int j = 0; j < 8; j++) acc[i][j] = 0.f;
    int lr = tid >> 1, lc = (tid & 1) << 2;
    for (int k0 = kLo; k0 < kHi; k0 += 8) {
        float4 av = *(const float4*)(Ab + (size_t)lr * lda + k0 + lc);
        float4 bv = *(const float4*)(Bb + (size_t)lr * ldb + k0 + lc);
        As[lc + 0][lr] = av.x; As[lc + 1][lr] = av.y; As[lc + 2][lr] = av.z; As[lc + 3][lr] = av.w;
        Bs[lc + 0][lr] = bv.x; Bs[lc + 1][lr] = bv.y; Bs[lc + 2][lr] = bv.z; Bs[lc + 3][lr] = bv.w;
        __syncthreads();
        #pragma unroll
        for (int k = 0; k < 8; k++) {
            float a[8], b[8];
            *(float4*)(a)     = *(const float4*)&As[k][ty * 8];
            *(float4*)(a + 4) = *(const float4*)&As[k][ty * 8 + 4];
            *(float4*)(b)     = *(const float4*)&Bs[k][tx * 8];
            *(float4*)(b + 4) = *(const float4*)&Bs[k][tx * 8 + 4];
            #pragma unroll
            for (int i = 0; i < 8; i++)
                #pragma unroll
                for (int j = 0; j < 8; j++) acc[i][j] += a[i] * b[j];
        }
        __syncthreads();
    }
    if (mode == 0) {
        #pragma unroll
        for (int i = 0; i < 8; i++) {
            float4* cp = (float4*)(Cb + (size_t)(ty * 8 + i) * ldc + tx * 8);
            float4 v0 = cp[0], v1 = cp[1];
            v0.x -= acc[i][0]; v0.y -= acc[i][1]; v0.z -= acc[i][2]; v0.w -= acc[i][3];
            v1.x -= acc[i][4]; v1.y -= acc[i][5]; v1.z -= acc[i][6]; v1.w -= acc[i][7];
            cp[0] = v0; cp[1] = v1;
        }
    } else {
        #pragma unroll
        for (int i = 0; i < 8; i++) {
            float4 v0, v1;
            v0.x = acc[i][0]; v0.y = acc[i][1]; v0.z = acc[i][2]; v0.w = acc[i][3];
            v1.x = acc[i][4]; v1.y = acc[i][5]; v1.z = acc[i][6]; v1.w = acc[i][7];
            float4* cp = (float4*)(Cb + (size_t)(ty * 8 + i) * ldc + tx * 8);
            cp[0] = v0; cp[1] = v1;
        }
    }
}

// ---------------- 128x128 diag Cholesky + blocked triangular inverse --------
// grid.x = batch. L diag block in/out (lda NPT); L^{-1} compact (ld 128).
__global__ void __launch_bounds__(128) potf2_inv(float* __restrict__ Lbase,
                                                 float* __restrict__ IvBase, int kblk) {
    int b = blockIdx.x;
    float* Ablk = Lbase + (size_t)b * LNN + (size_t)kblk * 128 * NPT + kblk * 128;
    float* IvBlk = IvBase + (size_t)b * LINB + kblk * 128 * 128;
    extern __shared__ float sm[];
    float* As = sm;                   // 128 x 129
    float* Iv = sm + 128 * 129;       // 128 x 128
    float* W  = sm + 128 * 129 + 128 * 128;   // 16 x 112
    int tid = threadIdx.x;
    for (int idx = tid; idx < 128 * 128; idx += 128) {
        int r = idx >> 7, c = idx & 127;
        As[r * 129 + c] = Ablk[(size_t)r * NPT + c];
        Iv[idx] = 0.f;
    }
    __syncthreads();
    for (int j = 0; j < 128; j++) {
        if (tid == 0) As[j * 129 + j] = sqrtf(As[j * 129 + j]);
        __syncthreads();
        float d = As[j * 129 + j];
        if (tid > j) As[tid * 129 + j] /= d;
        __syncthreads();
        int m = j + 1 + tid;
        if (m < 128) {
            float lm = As[m * 129 + j];
            #pragma unroll 4
            for (int t = j + 1; t < 128; t++)
                As[t * 129 + m] -= As[t * 129 + j] * lm;
        }
        __syncthreads();
    }
    // 16x16 diag block inverses
    {
        int db = tid >> 4, c = tid & 15, base = db * 16;
        for (int t = 0; t < 16; t++) {
            float v;
            if (t < c) v = 0.f;
            else if (t == c) v = 1.f / As[(base + t) * 129 + base + c];
            else {
                float s = 0.f;
                for (int m2 = c; m2 < t; m2++)
                    s += As[(base + t) * 129 + base + m2] * Iv[(base + m2) * 128 + base + c];
                v = -s / As[(base + t) * 129 + base + t];
            }
            Iv[(base + t) * 128 + base + c] = v;
        }
    }
    __syncthreads();
    // blocked forward substitution
    for (int tb = 1; tb < 8; tb++) {
        int R = tb * 16, ncol = tb * 16, total = 16 * ncol;
        for (int idx = tid; idx < total; idx += 128) {
            int s = idx / ncol, c2 = idx % ncol;
            float a = 0.f;
            for (int m2 = c2; m2 < R; m2++)
                a += As[(R + s) * 129 + m2] * Iv[m2 * 128 + c2];
            W[s * 112 + c2] = a;
        }
        __syncthreads();
        for (int idx = tid; idx < total; idx += 128) {
            int r = idx / ncol, c2 = idx % ncol;
            float a = 0.f;
            for (int s = 0; s <= r; s++)
                a += Iv[(R + r) * 128 + R + s] * W[s * 112 + c2];
            Iv[(R + r) * 128 + c2] = -a;
        }
        __syncthreads();
    }
    for (int idx = tid; idx < 128 * 128; idx += 128) {
        int r = idx >> 7, c = idx & 127;
        Ablk[(size_t)r * NPT + c] = As[r * 129 + c];
        IvBlk[idx] = Iv[idx];
    }
}

// ---------------- mu reduce: sum 8 split-K partials, transpose to out -------
__global__ void reduce_mu(const float* __restrict__ MUP, float* __restrict__ out) {
    int b = blockIdx.z;
    int idx = blockIdx.x * blockDim.x + threadIdx.x;   // 64*4096
    int dch = idx >> 12, p = idx & 4095;
    const float* base = MUP + (size_t)b * 8 * NPT * 128 + (size_t)p * 128 + dch;
    float s = 0.f;
    #pragma unroll
    for (int c = 0; c < 8; c++) s += base[(size_t)c * NPT * 128];
    out[(size_t)b * 89 * NPT + (size_t)dch * NPT + p] = s;
}

// ---------------- local covariance + Kxx on 5x5 neighborhoods ----------------
__global__ void __launch_bounds__(256) local_k(const float* __restrict__ Xg,
        const float* __restrict__ XFg, const float* __restrict__ xng,
        float* __restrict__ out) {
    int b = blockIdx.z;
    const float* X  = Xg  + (size_t)b * XNN;
    const float* XF = XFg + (size_t)b * NPT * 512;
    const float* xn = xng + (size_t)b * NPT;
    float* outb = out + (size_t)b * 89 * NPT;
    __shared__ __align__(16) float sXp[4096];
    __shared__ __align__(16) float sXf[512];
    __shared__ float sRed[16];
    int p = blockIdx.x, tid = threadIdx.x;
    const float4* Xp4 = (const float4*)(X + (size_t)p * NPT);
    for (int t = tid; t < 1024; t += 256) ((float4*)sXp)[t] = Xp4[t];
    const float4* xf4 = (const float4*)(XF + (size_t)p * 512);
    if (tid < 128) ((float4*)sXf)[tid] = xf4[tid];
    __syncthreads();
    int i0 = p >> 6, j0 = p & 63;
    float nxp = xn[p];
    int warp = tid >> 5, lane = tid & 31;
    for (int kk = 0; kk < 25; kk++) {
        int dr = kk / 5 - 2, dc = kk % 5 - 2;
        int qi = i0 + dr, qj = j0 + dc;
        bool valid = (qi >= 0) & (qi < 64) & (qj >= 0) & (qj < 64);
        __syncthreads();
        if (!valid) {
            if (tid == 0) outb[(size_t)(64 + kk) * NPT + p] = 0.f;
            continue;
        }
        int q = qi * 64 + qj;
        const float4* Xq4 = (const float4*)(X + (size_t)q * NPT);
        float s = 0.f;
        for (int t = tid; t < 1024; t += 256) {
            float4 a = ((const float4*)sXp)[t];
            float4 bq = Xq4[t];
            s += a.x * bq.x + a.y * bq.y + a.z * bq.z + a.w * bq.w;
        }
        float s2 = 0.f;
        const float4* xq4 = (const float4*)(XF + (size_t)q * 512);
        if (tid < 128) {
            float4 a = ((const float4*)sXf)[tid];
            float4 bq = xq4[tid];
            s2 = a.x * bq.x + a.y * bq.y + a.z * bq.z + a.w * bq.w;
        }
        #pragma unroll
        for (int o = 16; o; o >>= 1) {
            s  += __shfl_down_sync(0xffffffffu, s,  o);
            s2 += __shfl_down_sync(0xffffffffu, s2, o);
        }
        if (lane == 0) { sRed[warp] = s; sRed[8 + warp] = s2; }
        __syncthreads();
        if (tid == 0) {
            float ts = 0.f, ts2 = 0.f;
            #pragma unroll
            for (int w = 0; w < 8; w++) { ts += sRed[w]; ts2 += sRed[8 + w]; }
            float kxx = expf(ts2 / (nxp * xn[q] + 1e-6f) - 1.f);
            outb[(size_t)(64 + kk) * NPT + p] = kxx - ts;
        }
    }
}

// ---------------------------------------------------------------------------
extern "C" void kernel_launch(void* const* d_in, const int* in_sizes, int n_in,
                              void* d_out, int out_size) {
    const float* x  = (const float*)d_in[0];
    const float* y  = (const float*)d_in[1];
    const float* pw = (const float*)d_in[2];
    const float* pb = (const float*)d_in[3];
    float* out = (float*)d_out;
    (void)in_sizes; (void)n_in; (void)out_size;

    float *pL, *pX, *pLi, *pXF, *pMUP, *pxn, *pyn;
    cudaGetSymbolAddress((void**)&pL,   g_L);
    cudaGetSymbolAddress((void**)&pX,   g_X);
    cudaGetSymbolAddress((void**)&pLi,  g_Li);
    cudaGetSymbolAddress((void**)&pXF,  g_XF);
    cudaGetSymbolAddress((void**)&pMUP, g_MUP);
    cudaGetSymbolAddress((void**)&pxn,  g_xn);
    cudaGetSymbolAddress((void**)&pyn,  g_yn);

    const int PSMEM = (128 * 129 + 128 * 128 + 16 * 112) * 4;
    cudaFuncSetAttribute(potf2_inv, cudaFuncAttributeMaxDynamicSharedMemorySize, PSMEM);

    // ---- prep (both batches in every launch) ----
    norms2_k<<<dim3(16, 2, 2), 256>>>(x, y, pxn, pyn);
    transpose_k<<<dim3(128, 16, 2), dim3(32, 8)>>>(x, pXF);
    gram_tn<<<dim3(32, 32, 2), 256>>>(y, y, pL, pyn, pyn, 1, 0.1f, (long long)LNN);
    gram_tn<<<dim3(32, 32, 2), 256>>>(x, y, pX, pxn, pyn, 0, 0.f, (long long)XNN);
    features_k<<<dim3(1024, 1, 2), 256>>>(pw, pb, pX);
    zero_rows<<<dim3(1024, 1, 2), 256>>>(pX);

    // ---- blocked Cholesky (z-batched) ----
    for (int k = 0; k < NBLK; k++) {
        potf2_inv<<<2, 128, PSMEM>>>(pL, pLi, k);
        if (k < NBLK - 1) {
            int rem = NBLK - 1 - k;
            size_t panOff = (size_t)(k + 1) * 128 * NPT + k * 128;
            // L21 = A21 * iL11^T (in place)
            gemm_nt<<<dim3(1, rem, 2), 256>>>(pL + panOff, pLi + k * 128 * 128, pL + panOff,
                    128, NPT, 128, NPT, LNN, LINB, LNN, 1, 0, 0);
            // A22 -= L21 L21^T (lower)
            size_t trailOff = (size_t)(k + 1) * 128 * (NPT + 1);
            gemm_nt<<<dim3(rem, rem, 2), 256>>>(pL + panOff, pL + panOff, pL + trailOff,
                    128, NPT, NPT, NPT, LNN, LNN, LNN, 0, 1, 0);
        }
    }

    // ---- right-TRSM sweep: X <- X L^{-T} (z-batched) ----
    for (int k = 0; k < NBLK; k++) {
        size_t colOff = (size_t)k * 128;
        gemm_nt<<<dim3(1, MROWS / 128, 2), 256>>>(pX + colOff, pLi + k * 128 * 128, pX + colOff,
                128, NPT, 128, NPT, XNN, LINB, XNN, 1, 0, 0);
        if (k < NBLK - 1) {
            int rem = NBLK - 1 - k;
            size_t wOff = (size_t)(k + 1) * 128 * NPT + k * 128;
            size_t cOff = (size_t)(k + 1) * 128;
            gemm_nt<<<dim3(rem, MROWS / 128, 2), 256>>>(pX + colOff, pL + wOff, pX + cOff,
                    128, NPT, NPT, NPT, XNN, LNN, XNN, 0, 0, 0);
        }
    }

    // ---- mu: split-K (8 chunks of 512), then reduce ----
    gemm_nt<<<dim3(8, 32, 2), 256>>>(pX, pX + LNN, pMUP,
            NPT, NPT, NPT, 128, XNN, XNN, (long long)8 * NPT * 128, 1, 0, 512);
    reduce_mu<<<dim3(1024, 1, 2), 256>>>(pMUP, out);

    // ---- local covariance channels ----
    local_k<<<dim3(4096, 1, 2), 256>>>(pX, pXF, pxn, out);
}